// round 16
// baseline (speedup 1.0000x reference)
#include <cuda_runtime.h>
#include <cuda_fp16.h>
#include <cstdint>
#include <math.h>

#define BATCH 8
#define CH    2048
#define LPIX  784
#define DD    8192
#define NCLS  200
#define BM    128
#define NBLK  (CH / BM)                  // 16
#define NPAIR (NBLK * (NBLK + 1) / 2)    // 136
#define NCHUNK 25                        // 25 chunks of 32 cols (800 padded)

// slab layout: [b][bi(16)][chunk(25)][hi/lo(2)][128 rows][40 halves]
#define PLANE_H  (128 * 40)              // 5120 halves
#define PLANE_B  10240
#define SLAB_H   (2 * PLANE_H)           // 20480 bytes
#define SLAB_B   20480
__device__ __align__(16) __half d_xa[(size_t)BATCH * NBLK * NCHUNK * SLAB_H];  // 65.5 MB
__device__ float d_y[BATCH * DD];
__device__ float d_inv[BATCH];

// ============================ helpers ============================
__device__ __forceinline__ uint32_t s2u(const void* p) {
    uint32_t a;
    asm("{ .reg .u64 t; cvta.to.shared.u64 t, %1; cvt.u32.u64 %0, t; }" : "=r"(a) : "l"(p));
    return a;
}
__device__ __forceinline__ void ldsm4(uint32_t* r, uint32_t addr) {
    asm volatile("ldmatrix.sync.aligned.m8n8.x4.shared.b16 {%0,%1,%2,%3}, [%4];"
                 : "=r"(r[0]), "=r"(r[1]), "=r"(r[2]), "=r"(r[3]) : "r"(addr));
}
__device__ __forceinline__ void mma16816(float* c, const uint32_t* a, uint32_t b0, uint32_t b1) {
    asm volatile("mma.sync.aligned.m16n8k16.row.col.f32.f16.f16.f32 "
                 "{%0,%1,%2,%3}, {%4,%5,%6,%7}, {%8,%9}, {%0,%1,%2,%3};"
                 : "+f"(c[0]), "+f"(c[1]), "+f"(c[2]), "+f"(c[3])
                 : "r"(a[0]), "r"(a[1]), "r"(a[2]), "r"(a[3]), "r"(b0), "r"(b1));
}
__device__ __forceinline__ void red_shared_f32(uint32_t addr, float v) {
    asm volatile("red.shared.add.f32 [%0], %1;" :: "r"(addr), "f"(v) : "memory");
}
__device__ __forceinline__ void mbar_init(uint32_t a, uint32_t cnt) {
    asm volatile("mbarrier.init.shared.b64 [%0], %1;" :: "r"(a), "r"(cnt) : "memory");
}
__device__ __forceinline__ void mbar_expect_tx(uint32_t a, uint32_t bytes) {
    asm volatile("mbarrier.arrive.expect_tx.shared.b64 _, [%0], %1;" :: "r"(a), "r"(bytes) : "memory");
}
__device__ __forceinline__ void mbar_wait(uint32_t a, uint32_t parity) {
    asm volatile(
        "{\n\t.reg .pred P;\n\t"
        "LAB_%=:\n\t"
        "mbarrier.try_wait.parity.acquire.cta.shared::cta.b64 P, [%0], %1, 0x989680;\n\t"
        "@P bra.uni DONE_%=;\n\t"
        "bra.uni LAB_%=;\n\t"
        "DONE_%=:\n\t}"
        :: "r"(a), "r"(parity) : "memory");
}
__device__ __forceinline__ void bulk_g2s(uint32_t sdst, const void* gsrc, uint32_t bytes, uint32_t mbar) {
    asm volatile("cp.async.bulk.shared::cluster.global.mbarrier::complete_tx::bytes [%0], [%1], %2, [%3];"
                 :: "r"(sdst), "l"(gsrc), "r"(bytes), "r"(mbar) : "memory");
}

// smem: [stage0 30720][stage1 30720][bins 32768] = 94208  (bins have their own region,
// zeroed at kernel start under the first TMA wait — off the MMA->scatter critical boundary)
#define ARR_B    10240
#define STAGE_B  30720
#define BINS_OFF 61440
#define DYN_B    (BINS_OFF + DD * 4)     // 94208 -> 2 CTAs/SM (188KB)

// ============================ prep: fp32 -> fp16 hi/lo slabs + y/logit init ============================
__global__ __launch_bounds__(256) void prep_kernel(const float* __restrict__ x,
                                                   const float* __restrict__ bc,
                                                   float* __restrict__ out_logit) {
    size_t idx = (size_t)blockIdx.x * 256 + threadIdx.x;
    size_t total = (size_t)BATCH * CH * 200;
    if (idx >= total) return;

    if (idx < BATCH * DD) d_y[idx] = 0.f;
    if (out_logit && idx < BATCH * NCLS) out_logit[idx] = bc[idx % NCLS];

    int l4 = (int)(idx % 200);
    size_t bch = idx / 200;
    int ch = (int)(bch % CH);
    int b  = (int)(bch / CH);

    float4 v = make_float4(0.f, 0.f, 0.f, 0.f);
    if (l4 < 196) v = *(const float4*)(x + bch * LPIX + l4 * 4);

    __half2 h01 = make_half2(__float2half(v.x), __float2half(v.y));
    __half2 h23 = make_half2(__float2half(v.z), __float2half(v.w));
    __half2 l01 = make_half2(__float2half(v.x - __half2float(h01.x)),
                             __float2half(v.y - __half2float(h01.y)));
    __half2 l23 = make_half2(__float2half(v.z - __half2float(h23.x)),
                             __float2half(v.w - __half2float(h23.y)));

    int bi = ch >> 7, row = ch & 127;
    int l = l4 * 4;
    int c = l >> 5, colin = l & 31;
    size_t slab = ((size_t)(b * NBLK + bi) * NCHUNK + c) * SLAB_H;
    size_t hoff = slab + (size_t)row * 40 + colin;
    size_t loff = hoff + PLANE_H;
    *(__half2*)(d_xa + hoff)     = h01;
    *(__half2*)(d_xa + hoff + 2) = h23;
    *(__half2*)(d_xa + loff)     = l01;
    *(__half2*)(d_xa + loff + 2) = l23;
}

// ============================ fused Gram-MMA + count-sketch scatter ============================
__global__ __launch_bounds__(256, 2)
void gram_scatter_kernel(const float* __restrict__ s1, const float* __restrict__ s2,
                         const int* __restrict__ h1, const int* __restrict__ h2) {
    extern __shared__ __align__(16) char sraw[];
    __shared__ __align__(16) int4 rowinf[BM];   // {h1[ci]*4, bits(s1[ci]), h2[ci]*4, bits(s2[ci])}
    __shared__ int   h2c4[BM]; __shared__ float s2c[BM];   // columns
    __shared__ int   h1m4[BM]; __shared__ float s1m[BM];
    __shared__ __align__(8) unsigned long long mbar[2];

    int tid = threadIdx.x;
    int wid = tid >> 5, lane = tid & 31;
    int wm = wid >> 2, wn = wid & 3;             // 2 x 4 warp grid, warp tile 64x32
    int b = blockIdx.y;
    int pair = blockIdx.x;
    int bi = 0, rem = pair;
    while (rem >= NBLK - bi) { rem -= NBLK - bi; bi++; }
    int bj = bi + rem;

    uint32_t dyn_u = (s2u(sraw) + 127) & ~127u;
    char* dynp = sraw + (dyn_u - s2u(sraw));
    uint32_t mb[2] = { s2u(&mbar[0]), s2u(&mbar[1]) };
    float* binsf = (float*)(dynp + BINS_OFF);
    uint32_t bins_u = dyn_u + BINS_OFF;

    const __half* Aslab = d_xa + (size_t)(b * NBLK + bi) * NCHUNK * SLAB_H;
    const __half* Bslab = d_xa + (size_t)(b * NBLK + bj) * NCHUNK * SLAB_H;

    if (tid == 0) { mbar_init(mb[0], 1); mbar_init(mb[1], 1); }
    if (tid < BM) {
        int ci = bi * BM + tid, cj = bj * BM + tid;
        rowinf[tid] = make_int4(h1[ci] * 4, __float_as_int(s1[ci]),
                                h2[ci] * 4, __float_as_int(s2[ci]));
        h2c4[tid] = h2[cj] * 4; s2c[tid] = s2[cj];
        h1m4[tid] = h1[cj] * 4; s1m[tid] = s1[cj];
    }
    // zero bins up-front (hidden under first TMA wait; off the phase boundary)
    {
        float4 z4 = make_float4(0.f, 0.f, 0.f, 0.f);
        for (int i = tid * 4; i < DD; i += 1024) *(float4*)(binsf + i) = z4;
    }
    __syncthreads();

    float acc[4][4][4];
#pragma unroll
    for (int i = 0; i < 4; i++)
#pragma unroll
        for (int j = 0; j < 4; j++)
#pragma unroll
            for (int k = 0; k < 4; k++) acc[i][j][k] = 0.f;

    // bulk producer: A hi plane (10240 B) + B hi+lo slab (20480 B) per stage
    auto bulk_issue = [&](int chunk) {
        int st = chunk & 1;
        uint32_t sb = dyn_u + st * STAGE_B;
        mbar_expect_tx(mb[st], STAGE_B);
        bulk_g2s(sb,         Aslab + (size_t)chunk * SLAB_H, PLANE_B, mb[st]);
        bulk_g2s(sb + ARR_B, Bslab + (size_t)chunk * SLAB_H, SLAB_B,  mb[st]);
    };

    if (tid == 0) bulk_issue(0);

    int lrow = lane & 15, lk = lane >> 4;

    for (int c = 0; c < NCHUNK; c++) {
        int cur = c & 1;
        if (tid == 0 && c + 1 < NCHUNK) bulk_issue(c + 1);
        mbar_wait(mb[cur], (c >> 1) & 1);

        uint32_t base = dyn_u + cur * STAGE_B;
        uint32_t aHb = base;
        uint32_t bHb = base + ARR_B, bLb = base + 2 * ARR_B;

#pragma unroll
        for (int ks = 0; ks < 2; ks++) {
            uint32_t coff = (uint32_t)(ks * 16 + lk * 8) * 2;
            uint32_t bh[2][4], bl[2][4];
#pragma unroll
            for (int g = 0; g < 2; g++) {
                uint32_t r = (uint32_t)(wn * 32 + g * 16 + lrow);
                ldsm4(bh[g], bHb + r * 80 + coff);
                ldsm4(bl[g], bLb + r * 80 + coff);
            }
#pragma unroll
            for (int mf = 0; mf < 4; mf++) {
                uint32_t r = (uint32_t)(wm * 64 + mf * 16 + lrow);
                uint32_t ah[4];
                ldsm4(ah, aHb + r * 80 + coff);
#pragma unroll
                for (int nf = 0; nf < 4; nf++) {
                    int g = nf >> 1, s = nf & 1;
                    mma16816(acc[mf][nf], ah, bh[g][s], bh[g][s + 2]);
                    mma16816(acc[mf][nf], ah, bl[g][s], bl[g][s + 2]);
                }
            }
        }
        __syncthreads();   // all warps done with this stage before it is refilled
    }

    // ================= scatter into per-CTA smem bins (separate region, already zeroed) =================
    bool off = (bi != bj);
    int q = lane & 3, rbase = lane >> 2;

    int h2c48[8], h1m48[8];
    float s2c8[8], s1m8[8];
#pragma unroll
    for (int nf = 0; nf < 4; nf++)
#pragma unroll
        for (int e = 0; e < 2; e++) {
            int n = wn * 32 + nf * 8 + 2 * q + e;
            int id = nf * 2 + e;
            h2c48[id] = h2c4[n]; s2c8[id] = s2c[n];
            h1m48[id] = h1m4[n]; s1m8[id] = s1m[n];
        }

#pragma unroll
    for (int mf = 0; mf < 4; mf++) {
#pragma unroll
        for (int half = 0; half < 2; half++) {
            int m = wm * 64 + mf * 16 + rbase + half * 8;
            int4 ri = rowinf[m];
            int h1s = ri.x, h2s = ri.z;
            float s1v = __int_as_float(ri.y);
            float s2mv = __int_as_float(ri.w);
#pragma unroll
            for (int nf = 0; nf < 4; nf++)
#pragma unroll
                for (int e = 0; e < 2; e++) {
                    float v = acc[mf][nf][half * 2 + e];
                    int id = nf * 2 + e;
                    red_shared_f32(bins_u + (uint32_t)((h1s + h2c48[id]) & 0x7FFF),
                                   v * (s1v * s2c8[id]));
                    if (off) {
                        red_shared_f32(bins_u + (uint32_t)((h1m48[id] + h2s) & 0x7FFF),
                                       v * (s1m8[id] * s2mv));
                    }
                }
        }
    }
    __syncthreads();

    float* yb = d_y + b * DD;
    for (int i = tid * 4; i < DD; i += 1024) {
        float4 v = *(float4*)(binsf + i);
        if (v.x != 0.f) atomicAdd(&yb[i],     v.x);
        if (v.y != 0.f) atomicAdd(&yb[i + 1], v.y);
        if (v.z != 0.f) atomicAdd(&yb[i + 2], v.z);
        if (v.w != 0.f) atomicAdd(&yb[i + 3], v.w);
    }
}

// ============================ norm: inv = 1/max(sqrt(sum|y|), eps)  (feat^2 == |y|) ============================
__global__ __launch_bounds__(1024) void norm_kernel() {
    int b = blockIdx.x;
    int tid = threadIdx.x;
    __shared__ float red[32];

    const float* yb = d_y + b * DD;
    float ss = 0.f;
#pragma unroll
    for (int it = 0; it < 2; it++) {
        float4 v = *(const float4*)(yb + tid * 4 + it * 4096);
        ss += fabsf(v.x) + fabsf(v.y) + fabsf(v.z) + fabsf(v.w);
    }
#pragma unroll
    for (int o = 16; o > 0; o >>= 1) ss += __shfl_xor_sync(0xffffffffu, ss, o);
    if ((tid & 31) == 0) red[tid >> 5] = ss;
    __syncthreads();
    if (tid < 32) {
        float v = red[tid];
#pragma unroll
        for (int o = 16; o > 0; o >>= 1) v += __shfl_xor_sync(0xffffffffu, v, o);
        if (tid == 0) d_inv[b] = 1.f / fmaxf(sqrtf(v), 1e-12f);
    }
}

// ============================ classifier: n-split for 2x parallelism ============================
#define DCH 32
#define NHALF 100
__global__ __launch_bounds__(256) void classifier_kernel(const float* __restrict__ Wc,
                                                         float* __restrict__ out_logit,
                                                         float* __restrict__ out_feat) {
    __shared__ float ws[DCH * NHALF];      // 12.8 KB panel
    __shared__ float fs[BATCH][DCH];
    __shared__ float invs[BATCH];
    int tid = threadIdx.x;
    int d0 = blockIdx.x * DCH;
    int n0 = blockIdx.y * NHALF;

    if (tid < BATCH) invs[tid] = d_inv[tid];
    // load 32 x 100 panel of Wc (rows d0..d0+31, cols n0..n0+99), coalesced per row
    for (int i = tid; i < DCH * NHALF; i += 256) {
        int d = i / NHALF, n = i % NHALF;
        ws[i] = Wc[(size_t)(d0 + d) * NCLS + n0 + n];
    }
    __syncthreads();

    for (int i = tid; i < BATCH * DCH; i += 256) {
        int bb = i / DCH, dd = i % DCH;
        float v = d_y[(size_t)bb * DD + d0 + dd];
        float f = copysignf(sqrtf(fabsf(v)), v) * invs[bb];
        fs[bb][dd] = f;
        if (out_feat && blockIdx.y == 0) out_feat[(size_t)bb * DD + d0 + dd] = f;
    }
    __syncthreads();

    int n = tid;
    if (out_logit && n < NHALF) {
        float acc[BATCH];
#pragma unroll
        for (int bb = 0; bb < BATCH; bb++) acc[bb] = 0.f;
#pragma unroll 8
        for (int d = 0; d < DCH; d++) {
            float w = ws[d * NHALF + n];
#pragma unroll
            for (int bb = 0; bb < BATCH; bb++) acc[bb] += w * fs[bb][d];
        }
#pragma unroll
        for (int bb = 0; bb < BATCH; bb++)
            atomicAdd(&out_logit[bb * NCLS + n0 + n], acc[bb]);
    }
}

// ============================ launch ============================
extern "C" void kernel_launch(void* const* d_in, const int* in_sizes, int n_in,
                              void* d_out, int out_size) {
    const float* x  = (const float*)d_in[0];
    const float* s1 = (const float*)d_in[1];
    const float* s2 = (const float*)d_in[2];
    const float* Wc = (const float*)d_in[3];
    const float* bc = (const float*)d_in[4];
    const int*   h1 = (const int*)d_in[5];
    const int*   h2 = (const int*)d_in[6];

    float* out = (float*)d_out;
    float* out_logit = nullptr;
    float* out_feat  = nullptr;
    if (out_size >= BATCH * NCLS + BATCH * DD) {
        out_logit = out;
        out_feat  = out + BATCH * NCLS;
    } else if (out_size == BATCH * DD) {
        out_feat = out;
    } else {
        out_logit = out;
    }

    static bool attr_set = false;
    if (!attr_set) {
        cudaFuncSetAttribute(gram_scatter_kernel, cudaFuncAttributeMaxDynamicSharedMemorySize, DYN_B + 128);
        attr_set = true;
    }

    size_t prep_threads = (size_t)BATCH * CH * 200;
    prep_kernel<<<(unsigned)((prep_threads + 255) / 256), 256>>>(x, bc, out_logit);   // 1

    dim3 ggrid(NPAIR, BATCH);
    gram_scatter_kernel<<<ggrid, 256, DYN_B + 128>>>(s1, s2, h1, h2);                 // 2

    norm_kernel<<<BATCH, 1024>>>();                                                   // 3

    dim3 cgrid(DD / DCH, 2);
    classifier_kernel<<<cgrid, 256>>>(Wc, out_logit, out_feat);                       // 4
}

// round 17
// speedup vs baseline: 1.0084x; 1.0084x over previous
#include <cuda_runtime.h>
#include <cuda_fp16.h>
#include <cstdint>
#include <math.h>

#define BATCH 8
#define CH    2048
#define LPIX  784
#define DD    8192
#define NCLS  200
#define BM    128
#define NBLK  (CH / BM)                  // 16
#define NPAIR (NBLK * (NBLK + 1) / 2)    // 136
#define NCHUNK 25                        // 25 chunks of 32 cols (800 padded)

// slab layout: [b][bi(16)][chunk(25)][hi/lo(2)][128 rows][40 halves]
#define PLANE_H  (128 * 40)              // 5120 halves
#define PLANE_B  10240
#define SLAB_H   (2 * PLANE_H)           // 20480 bytes
#define SLAB_B   20480
__device__ __align__(16) __half d_xa[(size_t)BATCH * NBLK * NCHUNK * SLAB_H];  // 65.5 MB
__device__ float d_y[BATCH * DD];
__device__ float d_inv[BATCH];

// ============================ helpers ============================
__device__ __forceinline__ uint32_t s2u(const void* p) {
    uint32_t a;
    asm("{ .reg .u64 t; cvta.to.shared.u64 t, %1; cvt.u32.u64 %0, t; }" : "=r"(a) : "l"(p));
    return a;
}
__device__ __forceinline__ void ldsm4(uint32_t* r, uint32_t addr) {
    asm volatile("ldmatrix.sync.aligned.m8n8.x4.shared.b16 {%0,%1,%2,%3}, [%4];"
                 : "=r"(r[0]), "=r"(r[1]), "=r"(r[2]), "=r"(r[3]) : "r"(addr));
}
__device__ __forceinline__ void mma16816(float* c, const uint32_t* a, uint32_t b0, uint32_t b1) {
    asm volatile("mma.sync.aligned.m16n8k16.row.col.f32.f16.f16.f32 "
                 "{%0,%1,%2,%3}, {%4,%5,%6,%7}, {%8,%9}, {%0,%1,%2,%3};"
                 : "+f"(c[0]), "+f"(c[1]), "+f"(c[2]), "+f"(c[3])
                 : "r"(a[0]), "r"(a[1]), "r"(a[2]), "r"(a[3]), "r"(b0), "r"(b1));
}
__device__ __forceinline__ void red_shared_f32(uint32_t addr, float v) {
    asm volatile("red.shared.add.f32 [%0], %1;" :: "r"(addr), "f"(v) : "memory");
}
__device__ __forceinline__ void mbar_init(uint32_t a, uint32_t cnt) {
    asm volatile("mbarrier.init.shared.b64 [%0], %1;" :: "r"(a), "r"(cnt) : "memory");
}
__device__ __forceinline__ void mbar_expect_tx(uint32_t a, uint32_t bytes) {
    asm volatile("mbarrier.arrive.expect_tx.shared.b64 _, [%0], %1;" :: "r"(a), "r"(bytes) : "memory");
}
__device__ __forceinline__ void mbar_wait(uint32_t a, uint32_t parity) {
    asm volatile(
        "{\n\t.reg .pred P;\n\t"
        "LAB_%=:\n\t"
        "mbarrier.try_wait.parity.acquire.cta.shared::cta.b64 P, [%0], %1, 0x989680;\n\t"
        "@P bra.uni DONE_%=;\n\t"
        "bra.uni LAB_%=;\n\t"
        "DONE_%=:\n\t}"
        :: "r"(a), "r"(parity) : "memory");
}
__device__ __forceinline__ void bulk_g2s(uint32_t sdst, const void* gsrc, uint32_t bytes, uint32_t mbar) {
    asm volatile("cp.async.bulk.shared::cluster.global.mbarrier::complete_tx::bytes [%0], [%1], %2, [%3];"
                 :: "r"(sdst), "l"(gsrc), "r"(bytes), "r"(mbar) : "memory");
}

// smem: [stage0 30720][stage1 30720][bins 32768] = 94208  (bins separate; zeroed under first TMA wait)
#define ARR_B    10240
#define STAGE_B  30720
#define BINS_OFF 61440
#define DYN_B    (BINS_OFF + DD * 4)     // 94208 -> 2 CTAs/SM (188KB)

// ============================ prep: fp32 -> fp16 hi/lo slabs + y/logit init ============================
__global__ __launch_bounds__(256) void prep_kernel(const float* __restrict__ x,
                                                   const float* __restrict__ bc,
                                                   float* __restrict__ out_logit) {
    size_t idx = (size_t)blockIdx.x * 256 + threadIdx.x;
    size_t total = (size_t)BATCH * CH * 200;
    if (idx >= total) return;

    if (idx < BATCH * DD) d_y[idx] = 0.f;
    if (out_logit && idx < BATCH * NCLS) out_logit[idx] = bc[idx % NCLS];

    int l4 = (int)(idx % 200);
    size_t bch = idx / 200;
    int ch = (int)(bch % CH);
    int b  = (int)(bch / CH);

    float4 v = make_float4(0.f, 0.f, 0.f, 0.f);
    if (l4 < 196) v = *(const float4*)(x + bch * LPIX + l4 * 4);

    __half2 h01 = make_half2(__float2half(v.x), __float2half(v.y));
    __half2 h23 = make_half2(__float2half(v.z), __float2half(v.w));
    __half2 l01 = make_half2(__float2half(v.x - __half2float(h01.x)),
                             __float2half(v.y - __half2float(h01.y)));
    __half2 l23 = make_half2(__float2half(v.z - __half2float(h23.x)),
                             __float2half(v.w - __half2float(h23.y)));

    int bi = ch >> 7, row = ch & 127;
    int l = l4 * 4;
    int c = l >> 5, colin = l & 31;
    size_t slab = ((size_t)(b * NBLK + bi) * NCHUNK + c) * SLAB_H;
    size_t hoff = slab + (size_t)row * 40 + colin;
    size_t loff = hoff + PLANE_H;
    *(__half2*)(d_xa + hoff)     = h01;
    *(__half2*)(d_xa + hoff + 2) = h23;
    *(__half2*)(d_xa + loff)     = l01;
    *(__half2*)(d_xa + loff + 2) = l23;
}

// ============================ fused Gram-MMA + count-sketch scatter ============================
__global__ __launch_bounds__(256, 2)
void gram_scatter_kernel(const float* __restrict__ s1, const float* __restrict__ s2,
                         const int* __restrict__ h1, const int* __restrict__ h2) {
    extern __shared__ __align__(16) char sraw[];
    __shared__ __align__(16) int4 rowinf[BM];   // {h1[ci]*4, bits(s1[ci]), h2[ci]*4, bits(s2[ci])}
    __shared__ int   h2c4[BM]; __shared__ float s2c[BM];   // columns
    __shared__ int   h1m4[BM]; __shared__ float s1m[BM];
    __shared__ __align__(8) unsigned long long mbar[2];

    int tid = threadIdx.x;
    int wid = tid >> 5, lane = tid & 31;
    int wm = wid >> 2, wn = wid & 3;             // 2 x 4 warp grid, warp tile 64x32
    int b = blockIdx.y;
    int pair = blockIdx.x;
    int bi = 0, rem = pair;
    while (rem >= NBLK - bi) { rem -= NBLK - bi; bi++; }
    int bj = bi + rem;

    uint32_t dyn_u = (s2u(sraw) + 127) & ~127u;
    char* dynp = sraw + (dyn_u - s2u(sraw));
    uint32_t mb[2] = { s2u(&mbar[0]), s2u(&mbar[1]) };
    float* binsf = (float*)(dynp + BINS_OFF);
    uint32_t bins_u = dyn_u + BINS_OFF;

    const __half* Aslab = d_xa + (size_t)(b * NBLK + bi) * NCHUNK * SLAB_H;
    const __half* Bslab = d_xa + (size_t)(b * NBLK + bj) * NCHUNK * SLAB_H;

    if (tid == 0) { mbar_init(mb[0], 1); mbar_init(mb[1], 1); }
    if (tid < BM) {
        int ci = bi * BM + tid, cj = bj * BM + tid;
        rowinf[tid] = make_int4(h1[ci] * 4, __float_as_int(s1[ci]),
                                h2[ci] * 4, __float_as_int(s2[ci]));
        h2c4[tid] = h2[cj] * 4; s2c[tid] = s2[cj];
        h1m4[tid] = h1[cj] * 4; s1m[tid] = s1[cj];
    }
    // zero bins up-front (hidden under first TMA wait; off the phase boundary)
    {
        float4 z4 = make_float4(0.f, 0.f, 0.f, 0.f);
        for (int i = tid * 4; i < DD; i += 1024) *(float4*)(binsf + i) = z4;
    }
    __syncthreads();

    float acc[4][4][4];
#pragma unroll
    for (int i = 0; i < 4; i++)
#pragma unroll
        for (int j = 0; j < 4; j++)
#pragma unroll
            for (int k = 0; k < 4; k++) acc[i][j][k] = 0.f;

    // bulk producer: A hi plane (10240 B) + B hi+lo slab (20480 B) per stage
    auto bulk_issue = [&](int chunk) {
        int st = chunk & 1;
        uint32_t sb = dyn_u + st * STAGE_B;
        mbar_expect_tx(mb[st], STAGE_B);
        bulk_g2s(sb,         Aslab + (size_t)chunk * SLAB_H, PLANE_B, mb[st]);
        bulk_g2s(sb + ARR_B, Bslab + (size_t)chunk * SLAB_H, SLAB_B,  mb[st]);
    };

    if (tid == 0) bulk_issue(0);

    int lrow = lane & 15, lk = lane >> 4;

    for (int c = 0; c < NCHUNK; c++) {
        int cur = c & 1;
        if (tid == 0 && c + 1 < NCHUNK) bulk_issue(c + 1);
        mbar_wait(mb[cur], (c >> 1) & 1);

        uint32_t base = dyn_u + cur * STAGE_B;
        uint32_t aHb = base;
        uint32_t bHb = base + ARR_B, bLb = base + 2 * ARR_B;

#pragma unroll
        for (int ks = 0; ks < 2; ks++) {
            uint32_t coff = (uint32_t)(ks * 16 + lk * 8) * 2;
            uint32_t bh[2][4], bl[2][4];
#pragma unroll
            for (int g = 0; g < 2; g++) {
                uint32_t r = (uint32_t)(wn * 32 + g * 16 + lrow);
                ldsm4(bh[g], bHb + r * 80 + coff);
                ldsm4(bl[g], bLb + r * 80 + coff);
            }
#pragma unroll
            for (int mf = 0; mf < 4; mf++) {
                uint32_t r = (uint32_t)(wm * 64 + mf * 16 + lrow);
                uint32_t ah[4];
                ldsm4(ah, aHb + r * 80 + coff);
#pragma unroll
                for (int nf = 0; nf < 4; nf++) {
                    int g = nf >> 1, s = nf & 1;
                    mma16816(acc[mf][nf], ah, bh[g][s], bh[g][s + 2]);
                    mma16816(acc[mf][nf], ah, bl[g][s], bl[g][s + 2]);
                }
            }
        }
        __syncthreads();   // all warps done with this stage before it is refilled
    }

    // ================= scatter into per-CTA smem bins (separate region, already zeroed) =================
    bool off = (bi != bj);
    int q = lane & 3, rbase = lane >> 2;

    int h2c48[8], h1m48[8];
    float s2c8[8], s1m8[8];
#pragma unroll
    for (int nf = 0; nf < 4; nf++)
#pragma unroll
        for (int e = 0; e < 2; e++) {
            int n = wn * 32 + nf * 8 + 2 * q + e;
            int id = nf * 2 + e;
            h2c48[id] = h2c4[n]; s2c8[id] = s2c[n];
            h1m48[id] = h1m4[n]; s1m8[id] = s1m[n];
        }

#pragma unroll
    for (int mf = 0; mf < 4; mf++) {
#pragma unroll
        for (int half = 0; half < 2; half++) {
            int m = wm * 64 + mf * 16 + rbase + half * 8;
            int4 ri = rowinf[m];
            int h1s = ri.x, h2s = ri.z;
            float s1v = __int_as_float(ri.y);
            float s2mv = __int_as_float(ri.w);
#pragma unroll
            for (int nf = 0; nf < 4; nf++)
#pragma unroll
                for (int e = 0; e < 2; e++) {
                    float v = acc[mf][nf][half * 2 + e];
                    int id = nf * 2 + e;
                    red_shared_f32(bins_u + (uint32_t)((h1s + h2c48[id]) & 0x7FFF),
                                   v * (s1v * s2c8[id]));
                    if (off) {
                        red_shared_f32(bins_u + (uint32_t)((h1m48[id] + h2s) & 0x7FFF),
                                       v * (s1m8[id] * s2mv));
                    }
                }
        }
    }
    __syncthreads();

    float* yb = d_y + b * DD;
    for (int i = tid * 4; i < DD; i += 1024) {
        float4 v = *(float4*)(binsf + i);
        if (v.x != 0.f) atomicAdd(&yb[i],     v.x);
        if (v.y != 0.f) atomicAdd(&yb[i + 1], v.y);
        if (v.z != 0.f) atomicAdd(&yb[i + 2], v.z);
        if (v.w != 0.f) atomicAdd(&yb[i + 3], v.w);
    }
}

// ============================ norm: inv = 1/max(sqrt(sum|y|), eps)  (feat^2 == |y|) ============================
__global__ __launch_bounds__(1024) void norm_kernel() {
    int b = blockIdx.x;
    int tid = threadIdx.x;
    __shared__ float red[32];

    const float* yb = d_y + b * DD;
    float ss = 0.f;
#pragma unroll
    for (int it = 0; it < 2; it++) {
        float4 v = *(const float4*)(yb + tid * 4 + it * 4096);
        ss += fabsf(v.x) + fabsf(v.y) + fabsf(v.z) + fabsf(v.w);
    }
#pragma unroll
    for (int o = 16; o > 0; o >>= 1) ss += __shfl_xor_sync(0xffffffffu, ss, o);
    if ((tid & 31) == 0) red[tid >> 5] = ss;
    __syncthreads();
    if (tid < 32) {
        float v = red[tid];
#pragma unroll
        for (int o = 16; o > 0; o >>= 1) v += __shfl_xor_sync(0xffffffffu, v, o);
        if (tid == 0) d_inv[b] = 1.f / fmaxf(sqrtf(v), 1e-12f);
    }
}

// ============================ classifier: d-split (DCH=16, 512 blocks, contiguous W panels) ============================
#define DCH 16
__global__ __launch_bounds__(256) void classifier_kernel(const float* __restrict__ Wc,
                                                         float* __restrict__ out_logit,
                                                         float* __restrict__ out_feat) {
    __shared__ float ws[DCH * NCLS];      // 12.8 KB, single contiguous coalesced load
    __shared__ float fs[BATCH][DCH];
    __shared__ float invs[BATCH];
    int tid = threadIdx.x;
    int d0 = blockIdx.x * DCH;

    if (tid < BATCH) invs[tid] = d_inv[tid];
    for (int i = tid; i < DCH * NCLS; i += 256) ws[i] = Wc[(size_t)d0 * NCLS + i];
    for (int i = tid; i < BATCH * DCH; i += 256) {
        int bb = i / DCH, dd = i % DCH;
        float v = d_y[(size_t)bb * DD + d0 + dd];
        fs[bb][dd] = copysignf(sqrtf(fabsf(v)), v);
    }
    __syncthreads();

    // scale feats by inv and write out_feat (each block owns a distinct d-chunk)
    for (int i = tid; i < BATCH * DCH; i += 256) {
        int bb = i / DCH, dd = i % DCH;
        float f = fs[bb][dd] * invs[bb];
        fs[bb][dd] = f;
        if (out_feat) out_feat[(size_t)bb * DD + d0 + dd] = f;
    }
    __syncthreads();

    int n = tid;
    if (out_logit && n < NCLS) {
        float acc[BATCH];
#pragma unroll
        for (int bb = 0; bb < BATCH; bb++) acc[bb] = 0.f;
#pragma unroll
        for (int d = 0; d < DCH; d++) {
            float w = ws[d * NCLS + n];
#pragma unroll
            for (int bb = 0; bb < BATCH; bb++) acc[bb] += w * fs[bb][d];
        }
#pragma unroll
        for (int bb = 0; bb < BATCH; bb++)
            atomicAdd(&out_logit[bb * NCLS + n], acc[bb]);
    }
}

// ============================ launch ============================
extern "C" void kernel_launch(void* const* d_in, const int* in_sizes, int n_in,
                              void* d_out, int out_size) {
    const float* x  = (const float*)d_in[0];
    const float* s1 = (const float*)d_in[1];
    const float* s2 = (const float*)d_in[2];
    const float* Wc = (const float*)d_in[3];
    const float* bc = (const float*)d_in[4];
    const int*   h1 = (const int*)d_in[5];
    const int*   h2 = (const int*)d_in[6];

    float* out = (float*)d_out;
    float* out_logit = nullptr;
    float* out_feat  = nullptr;
    if (out_size >= BATCH * NCLS + BATCH * DD) {
        out_logit = out;
        out_feat  = out + BATCH * NCLS;
    } else if (out_size == BATCH * DD) {
        out_feat = out;
    } else {
        out_logit = out;
    }

    static bool attr_set = false;
    if (!attr_set) {
        cudaFuncSetAttribute(gram_scatter_kernel, cudaFuncAttributeMaxDynamicSharedMemorySize, DYN_B + 128);
        attr_set = true;
    }

    size_t prep_threads = (size_t)BATCH * CH * 200;
    prep_kernel<<<(unsigned)((prep_threads + 255) / 256), 256>>>(x, bc, out_logit);   // 1

    dim3 ggrid(NPAIR, BATCH);
    gram_scatter_kernel<<<ggrid, 256, DYN_B + 128>>>(s1, s2, h1, h2);                 // 2

    norm_kernel<<<BATCH, 1024>>>();                                                   // 3

    classifier_kernel<<<DD / DCH, 256>>>(Wc, out_logit, out_feat);                    // 4
}